// round 9
// baseline (speedup 1.0000x reference)
#include <cuda_runtime.h>
#include <cuda_bf16.h>
#include <math.h>
#include <stdint.h>

// Problem dims
#define BB 4096
#define UU 256
#define DD 128

// Fused GEMM: C[4096, 512] = A[4096, 384]bf16 . B[512, 384]bf16^T, fp32 accum
// K = 3*128 (hi*hi, hi*lo, lo*hi). B columns PAIR-interleaved (col 2u = W_u,
// col 2u+1 = bias_u) so each MMA (d0,d1) = (xw, xb).
// bf16 conversion, nv2, cons all computed IN-CTA; hyperbolic logit fused.
// smem: A hi/lo 4 chunks (64KB) + B hi/lo 4 chunks (64KB) + nv2 + cons.
// Logical chunk -> physical: pa = {0,1,0,1,2,3}, pb = {0,1,2,3,0,1}.
#define SM_A 0
#define SM_B 65536
#define SM_NV2 131072            // 128 floats
#define SM_CONS 131584           // 64 float4
#define GEMM_SMEM 132608

__device__ float g_logits[BB * UU];      // 4 MB logits (base-2 scaled)

// ---------------------------------------------------------------------------
// PTX helpers
// ---------------------------------------------------------------------------
__device__ __forceinline__ uint32_t smem_u32(const void* p) {
    uint32_t a;
    asm("{ .reg .u64 t; cvta.to.shared.u64 t, %1; cvt.u32.u64 %0, t; }"
        : "=r"(a) : "l"(p));
    return a;
}
#define LDSM4(r0, r1, r2, r3, addr) \
    asm volatile("ldmatrix.sync.aligned.m8n8.x4.shared.b16 {%0,%1,%2,%3}, [%4];" \
                 : "=r"(r0), "=r"(r1), "=r"(r2), "=r"(r3) : "r"(addr))
#define MMA16816(d0, d1, d2, d3, a0, a1, a2, a3, b0, b1) \
    asm volatile("mma.sync.aligned.m16n8k16.row.col.f32.bf16.bf16.f32 " \
                 "{%0,%1,%2,%3}, {%4,%5,%6,%7}, {%8,%9}, {%0,%1,%2,%3};" \
                 : "+f"(d0), "+f"(d1), "+f"(d2), "+f"(d3) \
                 : "r"(a0), "r"(a1), "r"(a2), "r"(a3), "r"(b0), "r"(b1))

__device__ __forceinline__ float fast_sqrt(float v) {
    float r;
    asm("sqrt.approx.f32 %0, %1;" : "=f"(r) : "f"(v));
    return r;
}

__device__ __forceinline__ void split_bf16(float v, __nv_bfloat16& hi, __nv_bfloat16& lo) {
    hi = __float2bfloat16(v);
    lo = __float2bfloat16(v - __bfloat162float(hi));
}

// split 8 fp32 -> hi/lo uint4 quads
__device__ __forceinline__ void split8(const float4 a, const float4 b,
                                       uint4& hq, uint4& lq) {
    union { __nv_bfloat16 h[8]; uint4 q; } hi, lo;
    float v[8] = {a.x, a.y, a.z, a.w, b.x, b.y, b.z, b.w};
    #pragma unroll
    for (int i = 0; i < 8; i++) split_bf16(v[i], hi.h[i], lo.h[i]);
    hq = hi.q;
    lq = lo.q;
}

// hyperbolic logit (base-2 scaled)
__device__ __forceinline__ float logit_f(float xw, float xb, float nv2,
                                         float nb2, float bw, float sww) {
    float beta = 1.0f - nb2;
    float bsw  = beta * sww;
    float t2 = -2.0f * xb;
    float alpha = 1.0f + t2 + nv2;
    float dd = 1.0f + t2 + nb2 * nv2;
    float num = 2.0f * beta * (beta * xw - alpha * bw);
    float smm_num = alpha * alpha * nb2 - 2.0f * alpha * beta * xb
                    + beta * beta * nv2;
    float arg = __fdividef(num * dd, (dd * dd - smm_num) * bsw);
    float s = arg + fast_sqrt(fmaf(arg, arg, 1.0f));
    return (2.0f * sww) * __log2f(s);
}

// ---------------------------------------------------------------------------
// Fused kernel: conversion + dual GEMM + hyperbolic epilogue.
// grid (4 ntiles, 32 mtiles), block 256 (8 warps). CTA = 128 rows x 64 u.
// ---------------------------------------------------------------------------
__global__ void __launch_bounds__(256)
gemm_kernel(const float* __restrict__ x,
            const float* __restrict__ W,
            const float* __restrict__ bias) {
    extern __shared__ __align__(1024) char smem[];
    uint32_t sbase = smem_u32(smem);
    float* snv2  = reinterpret_cast<float*>(smem + SM_NV2);
    float4* scons = reinterpret_cast<float4*>(smem + SM_CONS);

    const int tid = threadIdx.x;
    const int wid = tid >> 5, lane = tid & 31;
    const int ntile = blockIdx.x, mtile = blockIdx.y;

    // ===== Phase 1a: x -> A smem (hi chunk h, lo chunk 2+h) + nv2 =====
    {
        const int r0 = tid >> 4;      // 0..15
        const int kg = tid & 15;      // k16 group
        const int half = kg >> 3, k16 = kg & 7;
        const float4* x4 = reinterpret_cast<const float4*>(x)
                         + (mtile * 128) * 32 + kg * 2;
        #pragma unroll
        for (int rr = 0; rr < 8; rr++) {
            int rloc = rr * 16 + r0;
            float4 a = x4[rloc * 32];
            float4 b = x4[rloc * 32 + 1];
            uint4 hq, lq;
            split8(a, b, hq, lq);
            float s = a.x * a.x + a.y * a.y + a.z * a.z + a.w * a.w
                    + b.x * b.x + b.y * b.y + b.z * b.z + b.w * b.w;
            #pragma unroll
            for (int sh = 8; sh > 0; sh >>= 1)
                s += __shfl_xor_sync(0xffffffffu, s, sh);
            if (kg == 0) snv2[rloc] = s;
            int off16 = (rloc >> 3) * 64 + (rloc & 7) * 8 + (k16 ^ (rloc & 7));
            *reinterpret_cast<uint4*>(smem + SM_A + ((half) * 1024 + off16) * 16) = hq;
            *reinterpret_cast<uint4*>(smem + SM_A + ((2 + half) * 1024 + off16) * 16) = lq;
        }
    }

    // ===== Phase 1b: W/bias -> B smem (paired cols) + cons =====
    {
        const int u0 = tid >> 4;      // 0..15
        const int kg = tid & 15;
        const int half = kg >> 3, k16 = kg & 7;
        const float4* W4 = reinterpret_cast<const float4*>(W)
                         + (ntile * 64) * 32 + kg * 2;
        const float4* B4 = reinterpret_cast<const float4*>(bias)
                         + (ntile * 64) * 32 + kg * 2;
        #pragma unroll
        for (int rr = 0; rr < 4; rr++) {
            int ul = rr * 16 + u0;    // local u 0..63
            float4 wa = W4[ul * 32], wb = W4[ul * 32 + 1];
            float4 ba = B4[ul * 32], bb = B4[ul * 32 + 1];
            uint4 whq, wlq, bhq, blq;
            split8(wa, wb, whq, wlq);
            split8(ba, bb, bhq, blq);
            // cons partials over this thread's 8 k
            float nb2 = ba.x * ba.x + ba.y * ba.y + ba.z * ba.z + ba.w * ba.w
                      + bb.x * bb.x + bb.y * bb.y + bb.z * bb.z + bb.w * bb.w;
            float bw  = ba.x * wa.x + ba.y * wa.y + ba.z * wa.z + ba.w * wa.w
                      + bb.x * wb.x + bb.y * wb.y + bb.z * wb.z + bb.w * wb.w;
            float ww  = wa.x * wa.x + wa.y * wa.y + wa.z * wa.z + wa.w * wa.w
                      + wb.x * wb.x + wb.y * wb.y + wb.z * wb.z + wb.w * wb.w;
            #pragma unroll
            for (int sh = 8; sh > 0; sh >>= 1) {
                nb2 += __shfl_xor_sync(0xffffffffu, nb2, sh);
                bw  += __shfl_xor_sync(0xffffffffu, bw,  sh);
                ww  += __shfl_xor_sync(0xffffffffu, ww,  sh);
            }
            if (kg == 0) scons[ul] = make_float4(nb2, bw, sqrtf(ww), 0.0f);
            // W -> even col, bias -> odd col
            int nw = 2 * ul, nb = 2 * ul + 1;
            int offw = (nw >> 3) * 64 + (nw & 7) * 8 + (k16 ^ (nw & 7));
            int offb = (nb >> 3) * 64 + (nb & 7) * 8 + (k16 ^ (nb & 7));
            *reinterpret_cast<uint4*>(smem + SM_B + ((half) * 1024 + offw) * 16) = whq;
            *reinterpret_cast<uint4*>(smem + SM_B + ((2 + half) * 1024 + offw) * 16) = wlq;
            *reinterpret_cast<uint4*>(smem + SM_B + ((half) * 1024 + offb) * 16) = bhq;
            *reinterpret_cast<uint4*>(smem + SM_B + ((2 + half) * 1024 + offb) * 16) = blq;
        }
    }
    __syncthreads();

    // ===== Phase 2: mainloop (all data resident; no barriers) =====
    const int m0 = (wid & 1) * 64;
    const int n0 = (wid >> 1) * 32;
    const int rowa  = m0 + (lane & 15);
    const int abase = (rowa >> 3) * 64 + (rowa & 7) * 8;
    const int aswz  = rowa & 7;
    const int akus  = lane >> 4;
    const int rowb  = n0 + (lane & 7) + ((lane >> 4) << 3);
    const int bbase = (rowb >> 3) * 64 + (rowb & 7) * 8;
    const int bswz  = rowb & 7;
    const int bkus  = (lane >> 3) & 1;

    float d[4][4][4];
    #pragma unroll
    for (int i = 0; i < 4; i++)
        #pragma unroll
        for (int j = 0; j < 4; j++)
            #pragma unroll
            for (int q = 0; q < 4; q++) d[i][j][q] = 0.0f;

    const int pa[6] = {0, 1, 0, 1, 2, 3};   // logical chunk -> physical (A)
    const int pb[6] = {0, 1, 2, 3, 0, 1};   // (B)

    #pragma unroll
    for (int c = 0; c < 6; c++) {
        uint32_t aB = sbase + SM_A + pa[c] * 16384;
        uint32_t bB = sbase + SM_B + pb[c] * 16384;

        #pragma unroll
        for (int kk = 0; kk < 4; kk++) {
            uint32_t af[4][4];
            #pragma unroll
            for (int mf = 0; mf < 4; mf++) {
                uint32_t addr = aB + ((abase + mf * 128 +
                                       ((2 * kk + akus) ^ aswz)) << 4);
                LDSM4(af[mf][0], af[mf][1], af[mf][2], af[mf][3], addr);
            }
            uint32_t bf[2][4];
            #pragma unroll
            for (int h = 0; h < 2; h++) {
                uint32_t addr = bB + ((bbase + h * 128 +
                                       ((2 * kk + bkus) ^ bswz)) << 4);
                LDSM4(bf[h][0], bf[h][1], bf[h][2], bf[h][3], addr);
            }
            #pragma unroll
            for (int mf = 0; mf < 4; mf++)
                #pragma unroll
                for (int nf = 0; nf < 4; nf++)
                    MMA16816(d[mf][nf][0], d[mf][nf][1], d[mf][nf][2], d[mf][nf][3],
                             af[mf][0], af[mf][1], af[mf][2], af[mf][3],
                             bf[nf >> 1][(nf & 1) * 2], bf[nf >> 1][(nf & 1) * 2 + 1]);
        }
    }

    // ===== Phase 3: fused hyperbolic epilogue =====
    const int rloc0 = m0 + (lane >> 2);
    const int rbase = mtile * 128 + rloc0;
    const int ul0   = (wid >> 1) * 16 + (lane & 3);   // local u

    float4 cons[4];
    #pragma unroll
    for (int nf = 0; nf < 4; nf++)
        cons[nf] = scons[ul0 + nf * 4];
    float nv2a[4], nv2b[4];
    #pragma unroll
    for (int mf = 0; mf < 4; mf++) {
        nv2a[mf] = snv2[rloc0 + mf * 16];
        nv2b[mf] = snv2[rloc0 + mf * 16 + 8];
    }

    #pragma unroll
    for (int mf = 0; mf < 4; mf++)
        #pragma unroll
        for (int nf = 0; nf < 4; nf++) {
            int u = ntile * 64 + ul0 + nf * 4;
            float4 cs = cons[nf];
            g_logits[(rbase + mf * 16) * UU + u] =
                logit_f(d[mf][nf][0], d[mf][nf][1], nv2a[mf], cs.x, cs.y, cs.z);
            g_logits[(rbase + mf * 16 + 8) * UU + u] =
                logit_f(d[mf][nf][2], d[mf][nf][3], nv2b[mf], cs.x, cs.y, cs.z);
        }
}

// ---------------------------------------------------------------------------
// Softmax (base-2): one warp per row. grid 512, block 256 (8 rows/block).
// ---------------------------------------------------------------------------
__global__ void __launch_bounds__(256)
softmax_kernel(float* __restrict__ out) {
    const int wid = threadIdx.x >> 5, lane = threadIdx.x & 31;
    const int row = blockIdx.x * 8 + wid;

    const float* lrow = g_logits + row * UU;
    float v[8];
    float m = -1e30f;
    #pragma unroll
    for (int j = 0; j < 8; j++) {
        v[j] = lrow[lane + 32 * j];
        m = fmaxf(m, v[j]);
    }
    #pragma unroll
    for (int sh = 16; sh > 0; sh >>= 1)
        m = fmaxf(m, __shfl_xor_sync(0xffffffffu, m, sh));
    float e[8], s = 0.0f;
    #pragma unroll
    for (int j = 0; j < 8; j++) { e[j] = exp2f(v[j] - m); s += e[j]; }
    #pragma unroll
    for (int sh = 16; sh > 0; sh >>= 1)
        s += __shfl_xor_sync(0xffffffffu, s, sh);
    float inv = __fdividef(1.0f, s);
    #pragma unroll
    for (int j = 0; j < 8; j++)
        out[row * UU + lane + 32 * j] = e[j] * inv;
}

// ---------------------------------------------------------------------------
extern "C" void kernel_launch(void* const* d_in, const int* in_sizes, int n_in,
                              void* d_out, int out_size) {
    const float* x    = (const float*)d_in[0];
    const float* W    = (const float*)d_in[1];
    const float* bias = (const float*)d_in[2];
    float* out = (float*)d_out;

    cudaFuncSetAttribute(gemm_kernel,
                         cudaFuncAttributeMaxDynamicSharedMemorySize, GEMM_SMEM);

    gemm_kernel<<<dim3(4, 32), 256, GEMM_SMEM>>>(x, W, bias);
    softmax_kernel<<<BB / 8, 256>>>(out);
}